// round 1
// baseline (speedup 1.0000x reference)
#include <cuda_runtime.h>
#include <math.h>

#define DD   512
#define SS   2048
#define BB   2
#define HH   8
#define HDIM 64
#define GG   4
#define NROW (BB*SS)     // 4096
#define SP   68          // padded smem row stride (floats), 272B = 16B-aligned

// ---- scratch (device globals; no allocation allowed) ----
__device__ float g_q1[NROW*DD];
__device__ float g_k1[NROW*DD];
__device__ float g_q2[NROW*DD];
__device__ float g_k2[NROW*DD];
__device__ float g_v [NROW*DD];
__device__ float g_o [NROW*DD];
__device__ float g_mu  [BB*GG];
__device__ float g_rstd[BB*GG];

// ============================================================
// Kernel 1: fused 5-way projection GEMM  out = x @ W^T (+bias)
// grid (M/64, N/64, 5), block 256, 64x64x32 tiles, 4x4 microtile
// ============================================================
__global__ __launch_bounds__(256) void qkv_kernel(
    const float* __restrict__ x,
    const float* __restrict__ q1w,
    const float* __restrict__ k1w, const float* __restrict__ k1b,
    const float* __restrict__ q2w,
    const float* __restrict__ k2w, const float* __restrict__ k2b,
    const float* __restrict__ vw)
{
    __shared__ float As[32*SP];
    __shared__ float Bs[32*SP];

    const int tid = threadIdx.x;
    const int tx = tid & 15, ty = tid >> 4;
    const int m0 = blockIdx.x * 64;
    const int n0 = blockIdx.y * 64;
    const int p  = blockIdx.z;

    const float* W; const float* bias = nullptr; float* out;
    switch (p) {
        case 0:  W = q1w; out = g_q1; break;
        case 1:  W = k1w; bias = k1b; out = g_k1; break;
        case 2:  W = q2w; out = g_q2; break;
        case 3:  W = k2w; bias = k2b; out = g_k2; break;
        default: W = vw;  out = g_v;  break;
    }

    float acc[4][4] = {};

    for (int k0 = 0; k0 < DD; k0 += 32) {
        #pragma unroll
        for (int t = 0; t < 2; ++t) {
            int f = tid + t * 256;          // 0..511
            int row = f >> 3;               // 0..63
            int kk  = (f & 7) << 2;         // 0..28
            float4 a4 = *(const float4*)&x[(size_t)(m0+row)*DD + k0 + kk];
            As[(kk+0)*SP+row] = a4.x; As[(kk+1)*SP+row] = a4.y;
            As[(kk+2)*SP+row] = a4.z; As[(kk+3)*SP+row] = a4.w;
            float4 b4 = *(const float4*)&W[(size_t)(n0+row)*DD + k0 + kk];
            Bs[(kk+0)*SP+row] = b4.x; Bs[(kk+1)*SP+row] = b4.y;
            Bs[(kk+2)*SP+row] = b4.z; Bs[(kk+3)*SP+row] = b4.w;
        }
        __syncthreads();
        #pragma unroll 8
        for (int kk = 0; kk < 32; ++kk) {
            float4 a4 = *(const float4*)&As[kk*SP + 4*ty];
            float4 b4 = *(const float4*)&Bs[kk*SP + 4*tx];
            float a[4] = {a4.x, a4.y, a4.z, a4.w};
            float b[4] = {b4.x, b4.y, b4.z, b4.w};
            #pragma unroll
            for (int i = 0; i < 4; ++i)
                #pragma unroll
                for (int j = 0; j < 4; ++j)
                    acc[i][j] = fmaf(a[i], b[j], acc[i][j]);
        }
        __syncthreads();
    }

    float bv[4] = {0.f, 0.f, 0.f, 0.f};
    if (bias) {
        #pragma unroll
        for (int j = 0; j < 4; ++j) bv[j] = bias[n0 + 4*tx + j];
    }
    #pragma unroll
    for (int i = 0; i < 4; ++i) {
        float4 r;
        r.x = acc[i][0] + bv[0]; r.y = acc[i][1] + bv[1];
        r.z = acc[i][2] + bv[2]; r.w = acc[i][3] + bv[3];
        *(float4*)&out[(size_t)(m0 + 4*ty + i)*DD + n0 + 4*tx] = r;
    }
}

// ============================================================
// Kernel 2: dual-stream flash attention
// grid (S/64, B*H), block 256. 64q x 64k tiles, hd=64.
// ============================================================
__device__ __forceinline__ void attn_stream(
    const float* __restrict__ qT, const float* __restrict__ kT,
    const float* __restrict__ vsm, float* __restrict__ pT,
    int tx, int ty, float* m, float* l, float (*o)[4])
{
    float s[4][4] = {};
    #pragma unroll 8
    for (int kk = 0; kk < 64; ++kk) {
        float4 a4 = *(const float4*)&qT[kk*SP + 4*ty];
        float4 b4 = *(const float4*)&kT[kk*SP + 4*tx];
        float a[4] = {a4.x, a4.y, a4.z, a4.w};
        float b[4] = {b4.x, b4.y, b4.z, b4.w};
        #pragma unroll
        for (int i = 0; i < 4; ++i)
            #pragma unroll
            for (int j = 0; j < 4; ++j)
                s[i][j] = fmaf(a[i], b[j], s[i][j]);
    }
    // online softmax update (rows owned redundantly by 16 tx-lanes)
    #pragma unroll
    for (int i = 0; i < 4; ++i) {
        float tm = fmaxf(fmaxf(s[i][0], s[i][1]), fmaxf(s[i][2], s[i][3]));
        #pragma unroll
        for (int off = 8; off >= 1; off >>= 1)
            tm = fmaxf(tm, __shfl_xor_sync(0xffffffffu, tm, off));
        float mn   = fmaxf(m[i], tm);
        float corr = __expf(m[i] - mn);
        float rs = 0.f;
        #pragma unroll
        for (int j = 0; j < 4; ++j) {
            float pv = __expf(s[i][j] - mn);
            s[i][j] = pv; rs += pv;
        }
        #pragma unroll
        for (int off = 8; off >= 1; off >>= 1)
            rs += __shfl_xor_sync(0xffffffffu, rs, off);
        l[i] = l[i]*corr + rs;
        m[i] = mn;
        #pragma unroll
        for (int j = 0; j < 4; ++j) {
            o[i][j] *= corr;
            pT[(4*tx + j)*SP + 4*ty + i] = s[i][j];   // transposed p
        }
    }
    __syncthreads();
    // o += p @ v
    #pragma unroll 8
    for (int kk = 0; kk < 64; ++kk) {
        float4 a4 = *(const float4*)&pT[kk*SP + 4*ty];
        float4 b4 = *(const float4*)&vsm[kk*SP + 4*tx];
        float a[4] = {a4.x, a4.y, a4.z, a4.w};
        float b[4] = {b4.x, b4.y, b4.z, b4.w};
        #pragma unroll
        for (int i = 0; i < 4; ++i)
            #pragma unroll
            for (int j = 0; j < 4; ++j)
                o[i][j] = fmaf(a[i], b[j], o[i][j]);
    }
    __syncthreads();
}

__global__ __launch_bounds__(256, 2) void attn_kernel(
    const float* __restrict__ lq1, const float* __restrict__ lk1,
    const float* __restrict__ lq2, const float* __restrict__ lk2)
{
    extern __shared__ float sm[];
    float* q1T = sm;
    float* q2T = q1T + 64*SP;
    float* k1T = q2T + 64*SP;
    float* k2T = k1T + 64*SP;
    float* vsm = k2T + 64*SP;
    float* pT  = vsm + 64*SP;

    const int tid = threadIdx.x;
    const int tx = tid & 15, ty = tid >> 4;
    const int bh = blockIdx.y;
    const int b = bh >> 3, h = bh & 7;
    const int q0 = blockIdx.x * 64;

    const size_t qoff = (size_t)(b*SS + q0)*DD + h*HDIM;
    #pragma unroll
    for (int t = 0; t < 4; ++t) {
        int f = tid + t*256;
        int row = f >> 4;
        int kk  = (f & 15) << 2;
        size_t go = qoff + (size_t)row*DD + kk;
        float4 a = *(const float4*)&g_q1[go];
        q1T[(kk+0)*SP+row] = a.x*0.125f; q1T[(kk+1)*SP+row] = a.y*0.125f;
        q1T[(kk+2)*SP+row] = a.z*0.125f; q1T[(kk+3)*SP+row] = a.w*0.125f;
        float4 c = *(const float4*)&g_q2[go];
        q2T[(kk+0)*SP+row] = c.x*0.125f; q2T[(kk+1)*SP+row] = c.y*0.125f;
        q2T[(kk+2)*SP+row] = c.z*0.125f; q2T[(kk+3)*SP+row] = c.w*0.125f;
    }

    float o1[4][4] = {}, o2[4][4] = {};
    float m1[4], l1[4], m2[4], l2[4];
    #pragma unroll
    for (int i = 0; i < 4; ++i) {
        m1[i] = -1e30f; l1[i] = 0.f;
        m2[i] = -1e30f; l2[i] = 0.f;
    }

    for (int kc = 0; kc < SS; kc += 64) {
        const size_t koff = (size_t)(b*SS + kc)*DD + h*HDIM;
        #pragma unroll
        for (int t = 0; t < 4; ++t) {
            int f = tid + t*256;
            int row = f >> 4;
            int kk  = (f & 15) << 2;
            size_t go = koff + (size_t)row*DD + kk;
            float4 a = *(const float4*)&g_k1[go];
            k1T[(kk+0)*SP+row] = a.x; k1T[(kk+1)*SP+row] = a.y;
            k1T[(kk+2)*SP+row] = a.z; k1T[(kk+3)*SP+row] = a.w;
            float4 c = *(const float4*)&g_k2[go];
            k2T[(kk+0)*SP+row] = c.x; k2T[(kk+1)*SP+row] = c.y;
            k2T[(kk+2)*SP+row] = c.z; k2T[(kk+3)*SP+row] = c.w;
            float4 v4 = *(const float4*)&g_v[go];
            *(float4*)&vsm[row*SP + kk] = v4;     // natural [key][hd]
        }
        __syncthreads();
        attn_stream(q1T, k1T, vsm, pT, tx, ty, m1, l1, o1);
        attn_stream(q2T, k2T, vsm, pT, tx, ty, m2, l2, o2);
    }

    const float lam = __expf(lq1[h]*lk1[h]) - __expf(lq2[h]*lk2[h]) + 0.2f;
    float* og = g_o + (size_t)(b*SS + q0)*DD + h*HDIM;
    #pragma unroll
    for (int i = 0; i < 4; ++i) {
        float i1 = 1.f / l1[i];
        float i2 = lam / l2[i];
        float4 r;
        r.x = o1[i][0]*i1 - o2[i][0]*i2;
        r.y = o1[i][1]*i1 - o2[i][1]*i2;
        r.z = o1[i][2]*i1 - o2[i][2]*i2;
        r.w = o1[i][3]*i1 - o2[i][3]*i2;
        *(float4*)&og[(size_t)(4*ty + i)*DD + 4*tx] = r;
    }
}

// ============================================================
// Kernel 3: GroupNorm stats (mean/rstd per (b,g) over 128ch x S)
// ============================================================
__global__ __launch_bounds__(256) void gn_stats_kernel()
{
    const int gi = blockIdx.x;           // 0..7
    const int b = gi >> 2, g = gi & 3;
    const int tid = threadIdx.x;
    const float* base = g_o + (size_t)b*SS*DD + g*128;

    float s = 0.f, ss = 0.f;
    for (int i = tid; i < SS*128; i += 256) {
        int r = i >> 7, c = i & 127;
        float v = base[(size_t)r*DD + c];
        s += v; ss += v*v;
    }
    __shared__ float rs[256], rq[256];
    rs[tid] = s; rq[tid] = ss;
    __syncthreads();
    for (int off = 128; off > 0; off >>= 1) {
        if (tid < off) { rs[tid] += rs[tid+off]; rq[tid] += rq[tid+off]; }
        __syncthreads();
    }
    if (tid == 0) {
        const float n = (float)(SS*128);
        float mu  = rs[0] / n;
        float var = rq[0] / n - mu*mu;
        g_mu[gi]   = mu;
        g_rstd[gi] = rsqrtf(var + 1e-5f);
    }
}

// ============================================================
// Kernel 4: output GEMM with GroupNorm fused into A-tile load
// y = norm(o) @ out_w^T + out_b
// ============================================================
__global__ __launch_bounds__(256) void out_kernel(
    const float* __restrict__ W, const float* __restrict__ bias,
    const float* __restrict__ gw, const float* __restrict__ gb,
    float* __restrict__ y)
{
    __shared__ float As[32*SP];
    __shared__ float Bs[32*SP];

    const int tid = threadIdx.x;
    const int tx = tid & 15, ty = tid >> 4;
    const int m0 = blockIdx.x * 64;
    const int n0 = blockIdx.y * 64;
    const int b  = m0 >> 11;             // 2048 rows per batch, 64 | 2048

    float acc[4][4] = {};

    for (int k0 = 0; k0 < DD; k0 += 32) {
        #pragma unroll
        for (int t = 0; t < 2; ++t) {
            int f = tid + t * 256;
            int row = f >> 3;
            int kk  = (f & 7) << 2;
            int c   = k0 + kk;                 // channel base (4 chans, same group)
            int gi  = b*4 + (c >> 7);
            float mu = g_mu[gi], rst = g_rstd[gi];
            float4 a4 = *(const float4*)&g_o[(size_t)(m0+row)*DD + c];
            float4 w4 = *(const float4*)&gw[c];
            float4 s4 = *(const float4*)&gb[c];
            As[(kk+0)*SP+row] = (a4.x - mu)*rst*w4.x + s4.x;
            As[(kk+1)*SP+row] = (a4.y - mu)*rst*w4.y + s4.y;
            As[(kk+2)*SP+row] = (a4.z - mu)*rst*w4.z + s4.z;
            As[(kk+3)*SP+row] = (a4.w - mu)*rst*w4.w + s4.w;
            float4 b4 = *(const float4*)&W[(size_t)(n0+row)*DD + k0 + kk];
            Bs[(kk+0)*SP+row] = b4.x; Bs[(kk+1)*SP+row] = b4.y;
            Bs[(kk+2)*SP+row] = b4.z; Bs[(kk+3)*SP+row] = b4.w;
        }
        __syncthreads();
        #pragma unroll 8
        for (int kk = 0; kk < 32; ++kk) {
            float4 a4 = *(const float4*)&As[kk*SP + 4*ty];
            float4 b4 = *(const float4*)&Bs[kk*SP + 4*tx];
            float a[4] = {a4.x, a4.y, a4.z, a4.w};
            float bb[4] = {b4.x, b4.y, b4.z, b4.w};
            #pragma unroll
            for (int i = 0; i < 4; ++i)
                #pragma unroll
                for (int j = 0; j < 4; ++j)
                    acc[i][j] = fmaf(a[i], bb[j], acc[i][j]);
        }
        __syncthreads();
    }

    float bv[4];
    #pragma unroll
    for (int j = 0; j < 4; ++j) bv[j] = bias[n0 + 4*tx + j];
    #pragma unroll
    for (int i = 0; i < 4; ++i) {
        float4 r;
        r.x = acc[i][0] + bv[0]; r.y = acc[i][1] + bv[1];
        r.z = acc[i][2] + bv[2]; r.w = acc[i][3] + bv[3];
        *(float4*)&y[(size_t)(m0 + 4*ty + i)*DD + n0 + 4*tx] = r;
    }
}

// ============================================================
// launch
// ============================================================
extern "C" void kernel_launch(void* const* d_in, const int* in_sizes, int n_in,
                              void* d_out, int out_size)
{
    const float* x   = (const float*)d_in[0];
    const float* K1w = (const float*)d_in[1];
    const float* K1b = (const float*)d_in[2];
    const float* Q1w = (const float*)d_in[3];
    const float* K2w = (const float*)d_in[4];
    const float* K2b = (const float*)d_in[5];
    const float* Q2w = (const float*)d_in[6];
    const float* Vw  = (const float*)d_in[7];
    const float* lq1 = (const float*)d_in[8];
    const float* lk1 = (const float*)d_in[9];
    const float* lq2 = (const float*)d_in[10];
    const float* lk2 = (const float*)d_in[11];
    const float* gw  = (const float*)d_in[12];
    const float* gb  = (const float*)d_in[13];
    const float* Ow  = (const float*)d_in[14];
    const float* Ob  = (const float*)d_in[15];
    float* y = (float*)d_out;

    const int ATT_SMEM = 6 * 64 * SP * (int)sizeof(float);   // 104448 B
    cudaFuncSetAttribute(attn_kernel,
                         cudaFuncAttributeMaxDynamicSharedMemorySize, ATT_SMEM);

    qkv_kernel<<<dim3(64, 8, 5), 256>>>(x, Q1w, K1w, K1b, Q2w, K2w, K2b, Vw);
    attn_kernel<<<dim3(SS/64, BB*HH), 256, ATT_SMEM>>>(lq1, lk1, lq2, lk2);
    gn_stats_kernel<<<BB*GG, 256>>>();
    out_kernel<<<dim3(64, 8), 256>>>(Ow, Ob, gw, gb, y);
}

// round 3
// speedup vs baseline: 2.3034x; 2.3034x over previous
#include <cuda_runtime.h>
#include <cuda_bf16.h>
#include <math.h>

#define DD   512
#define SS   2048
#define BB   2
#define HH   8
#define GG   4
#define NROW (BB*SS)     // 4096
#define SP   68          // fp32 smem row stride (out_kernel)
#define SR   72          // bf16 smem row stride (144B: conflict-free ldmatrix)

typedef unsigned int u32;

// ---- scratch (device globals; no allocation allowed) ----
__device__ __nv_bfloat16 g_q1h[NROW*DD], g_q1l[NROW*DD];
__device__ __nv_bfloat16 g_q2h[NROW*DD], g_q2l[NROW*DD];
__device__ __nv_bfloat16 g_k1h[NROW*DD], g_k1l[NROW*DD];
__device__ __nv_bfloat16 g_k2h[NROW*DD], g_k2l[NROW*DD];
__device__ __nv_bfloat16 g_vth[BB*HH*64*SS], g_vtl[BB*HH*64*SS];  // [bh][hd][seq]
__device__ float g_o [NROW*DD];
__device__ float g_mu  [BB*GG];
__device__ float g_rstd[BB*GG];

// ============================================================
// helpers
// ============================================================
__device__ __forceinline__ unsigned smem_u32(const void* p) {
    return (unsigned)__cvta_generic_to_shared(p);
}
__device__ __forceinline__ void ldsm4(u32& r0, u32& r1, u32& r2, u32& r3, unsigned a) {
    asm volatile("ldmatrix.sync.aligned.m8n8.x4.shared.b16 {%0,%1,%2,%3}, [%4];"
                 : "=r"(r0), "=r"(r1), "=r"(r2), "=r"(r3) : "r"(a));
}
__device__ __forceinline__ void mma_bf16(float* c, const u32* a, u32 b0, u32 b1) {
    asm volatile("mma.sync.aligned.m16n8k16.row.col.f32.bf16.bf16.f32 "
                 "{%0,%1,%2,%3},{%4,%5,%6,%7},{%8,%9},{%0,%1,%2,%3};"
                 : "+f"(c[0]), "+f"(c[1]), "+f"(c[2]), "+f"(c[3])
                 : "r"(a[0]), "r"(a[1]), "r"(a[2]), "r"(a[3]), "r"(b0), "r"(b1));
}
__device__ __forceinline__ void split1(float v, __nv_bfloat16& h, __nv_bfloat16& l) {
    h = __float2bfloat16(v);
    l = __float2bfloat16(v - __bfloat162float(h));
}
__device__ __forceinline__ void split2(float x, float y, u32& h, u32& l) {
    __nv_bfloat162 hh = __floats2bfloat162_rn(x, y);   // .x = low half
    float2 hf = __bfloat1622float2(hh);
    __nv_bfloat162 ll = __floats2bfloat162_rn(x - hf.x, y - hf.y);
    h = *(u32*)&hh; l = *(u32*)&ll;
}

// ============================================================
// Kernel 1: fused 5-way projection GEMM (bf16x3 tensor cores)
// out = x @ W^T (+bias) (*scale); writes split bf16 hi/lo.
// grid (M/64, N/64, 5), block 128 (4 warps), 64x64x64 tiles.
// ============================================================
__global__ __launch_bounds__(128) void qkv_mma_kernel(
    const float* __restrict__ x,
    const float* __restrict__ q1w,
    const float* __restrict__ k1w, const float* __restrict__ k1b,
    const float* __restrict__ q2w,
    const float* __restrict__ k2w, const float* __restrict__ k2b,
    const float* __restrict__ vw)
{
    __shared__ __nv_bfloat16 Ah[64*SR], Al[64*SR], Bh[64*SR], Bl[64*SR];

    const int tid = threadIdx.x;
    const int lane = tid & 31, warp = tid >> 5;
    const int m0 = blockIdx.x * 64, n0 = blockIdx.y * 64, p = blockIdx.z;

    const float* W; const float* bias = nullptr; float scale = 1.f;
    switch (p) {
        case 0:  W = q1w; scale = 0.125f; break;
        case 1:  W = k1w; bias = k1b; break;
        case 2:  W = q2w; scale = 0.125f; break;
        case 3:  W = k2w; bias = k2b; break;
        default: W = vw; break;
    }

    float c[8][4] = {};

    const unsigned ah_b = smem_u32(Ah), al_b = smem_u32(Al);
    const unsigned bh_b = smem_u32(Bh), bl_b = smem_u32(Bl);
    const int arow   = warp*16 + (lane & 7) + ((lane >> 3) & 1) * 8;
    const int acol   = ((lane >> 4) << 3);
    const int browin = (lane & 7) + ((lane >> 4) << 3);
    const int bcol   = (((lane >> 3) & 1) << 3);

    for (int k0 = 0; k0 < DD; k0 += 64) {
        #pragma unroll
        for (int it = 0; it < 8; ++it) {
            int idx = tid + it * 128;         // 0..1023
            int row = idx >> 4, c4 = (idx & 15) << 2;
            float4 a = *(const float4*)&x[(size_t)(m0+row)*DD + k0 + c4];
            split1(a.x, Ah[row*SR+c4+0], Al[row*SR+c4+0]);
            split1(a.y, Ah[row*SR+c4+1], Al[row*SR+c4+1]);
            split1(a.z, Ah[row*SR+c4+2], Al[row*SR+c4+2]);
            split1(a.w, Ah[row*SR+c4+3], Al[row*SR+c4+3]);
            float4 w = *(const float4*)&W[(size_t)(n0+row)*DD + k0 + c4];
            split1(w.x, Bh[row*SR+c4+0], Bl[row*SR+c4+0]);
            split1(w.y, Bh[row*SR+c4+1], Bl[row*SR+c4+1]);
            split1(w.z, Bh[row*SR+c4+2], Bl[row*SR+c4+2]);
            split1(w.w, Bh[row*SR+c4+3], Bl[row*SR+c4+3]);
        }
        __syncthreads();

        #pragma unroll
        for (int ks = 0; ks < 4; ++ks) {
            unsigned aoff = (unsigned)((arow*SR + ks*16 + acol) * 2);
            u32 aH[4], aL[4];
            ldsm4(aH[0],aH[1],aH[2],aH[3], ah_b + aoff);
            ldsm4(aL[0],aL[1],aL[2],aL[3], al_b + aoff);
            #pragma unroll
            for (int np = 0; np < 4; ++np) {
                unsigned boff = (unsigned)(((np*16 + browin)*SR + ks*16 + bcol) * 2);
                u32 bH[4], bL[4];
                ldsm4(bH[0],bH[1],bH[2],bH[3], bh_b + boff);
                ldsm4(bL[0],bL[1],bL[2],bL[3], bl_b + boff);
                mma_bf16(c[2*np],   aH, bH[0], bH[1]);
                mma_bf16(c[2*np],   aH, bL[0], bL[1]);
                mma_bf16(c[2*np],   aL, bH[0], bH[1]);
                mma_bf16(c[2*np+1], aH, bH[2], bH[3]);
                mma_bf16(c[2*np+1], aH, bL[2], bL[3]);
                mma_bf16(c[2*np+1], aL, bH[2], bH[3]);
            }
        }
        __syncthreads();
    }

    const int gid = lane >> 2, tig = lane & 3;
    if (p == 4) {
        // V: write transposed split bf16: g_vt[(b*8+h)*64+hd][seq]
        #pragma unroll
        for (int nf = 0; nf < 8; ++nf)
            #pragma unroll
            for (int e = 0; e < 4; ++e) {
                int r = m0 + warp*16 + gid + (e >> 1) * 8;
                int n = n0 + nf*8 + tig*2 + (e & 1);
                int bb = r >> 11, seq = r & 2047;
                int hh = n >> 6,  hd  = n & 63;
                size_t o = ((size_t)((bb*HH + hh)*64 + hd))*SS + seq;
                __nv_bfloat16 hi, lo; split1(c[nf][e], hi, lo);
                g_vth[o] = hi; g_vtl[o] = lo;
            }
    } else {
        __nv_bfloat16 *oh, *ol;
        switch (p) {
            case 0:  oh = g_q1h; ol = g_q1l; break;
            case 1:  oh = g_k1h; ol = g_k1l; break;
            case 2:  oh = g_q2h; ol = g_q2l; break;
            default: oh = g_k2h; ol = g_k2l; break;
        }
        #pragma unroll
        for (int nf = 0; nf < 8; ++nf)
            #pragma unroll
            for (int hf = 0; hf < 2; ++hf) {
                int r = m0 + warp*16 + gid + hf*8;
                int n = n0 + nf*8 + tig*2;
                float b0 = bias ? bias[n]   : 0.f;
                float b1 = bias ? bias[n+1] : 0.f;
                float v0 = c[nf][2*hf]   * scale + b0;
                float v1 = c[nf][2*hf+1] * scale + b1;
                u32 h, l; split2(v0, v1, h, l);
                *(u32*)&oh[(size_t)r*DD + n] = h;
                *(u32*)&ol[(size_t)r*DD + n] = l;
            }
    }
}

// ============================================================
// Kernel 2: dual-stream flash attention (bf16x3 tensor cores)
// grid (S/64, B*H), block 128 (4 warps). 64q x 64k tiles, hd=64.
// ============================================================
__device__ __forceinline__ void attn_stream_tc(
    unsigned qh_b, unsigned ql_b, unsigned kh_b, unsigned kl_b,
    unsigned vh_b, unsigned vl_b,
    int arow, int acol, int browin, int bcol,
    float* m, float* l, float (*o)[4])
{
    float c[8][4] = {};
    // S = q @ k^T  (scale pre-folded into q)
    #pragma unroll
    for (int ks = 0; ks < 4; ++ks) {
        unsigned aoff = (unsigned)((arow*SR + ks*16 + acol) * 2);
        u32 aH[4], aL[4];
        ldsm4(aH[0],aH[1],aH[2],aH[3], qh_b + aoff);
        ldsm4(aL[0],aL[1],aL[2],aL[3], ql_b + aoff);
        #pragma unroll
        for (int np = 0; np < 4; ++np) {
            unsigned boff = (unsigned)(((np*16 + browin)*SR + ks*16 + bcol) * 2);
            u32 bH[4], bL[4];
            ldsm4(bH[0],bH[1],bH[2],bH[3], kh_b + boff);
            ldsm4(bL[0],bL[1],bL[2],bL[3], kl_b + boff);
            mma_bf16(c[2*np],   aH, bH[0], bH[1]);
            mma_bf16(c[2*np],   aH, bL[0], bL[1]);
            mma_bf16(c[2*np],   aL, bH[0], bH[1]);
            mma_bf16(c[2*np+1], aH, bH[2], bH[3]);
            mma_bf16(c[2*np+1], aH, bL[2], bL[3]);
            mma_bf16(c[2*np+1], aL, bH[2], bH[3]);
        }
    }
    // online softmax (each thread owns rows r0=gid, r1=gid+8; 4 lanes/row)
    #pragma unroll
    for (int hf = 0; hf < 2; ++hf) {
        float mx = -1e30f;
        #pragma unroll
        for (int nf = 0; nf < 8; ++nf)
            mx = fmaxf(mx, fmaxf(c[nf][2*hf], c[nf][2*hf+1]));
        mx = fmaxf(mx, __shfl_xor_sync(0xffffffffu, mx, 1));
        mx = fmaxf(mx, __shfl_xor_sync(0xffffffffu, mx, 2));
        float mn   = fmaxf(m[hf], mx);
        float corr = __expf(m[hf] - mn);
        float rs = 0.f;
        #pragma unroll
        for (int nf = 0; nf < 8; ++nf) {
            float p0 = __expf(c[nf][2*hf]   - mn);
            float p1 = __expf(c[nf][2*hf+1] - mn);
            c[nf][2*hf] = p0; c[nf][2*hf+1] = p1;
            rs += p0 + p1;
        }
        rs += __shfl_xor_sync(0xffffffffu, rs, 1);
        rs += __shfl_xor_sync(0xffffffffu, rs, 2);
        l[hf] = l[hf]*corr + rs;
        m[hf] = mn;
        #pragma unroll
        for (int nf = 0; nf < 8; ++nf) {
            o[nf][2*hf]   *= corr;
            o[nf][2*hf+1] *= corr;
        }
    }
    // O += P @ V   (P A-fragments come straight from the S accumulators)
    #pragma unroll
    for (int ks = 0; ks < 4; ++ks) {
        u32 pH[4], pL[4];
        split2(c[2*ks][0],   c[2*ks][1],   pH[0], pL[0]);
        split2(c[2*ks][2],   c[2*ks][3],   pH[1], pL[1]);
        split2(c[2*ks+1][0], c[2*ks+1][1], pH[2], pL[2]);
        split2(c[2*ks+1][2], c[2*ks+1][3], pH[3], pL[3]);
        #pragma unroll
        for (int np = 0; np < 4; ++np) {
            unsigned boff = (unsigned)(((np*16 + browin)*SR + ks*16 + bcol) * 2);
            u32 bH[4], bL[4];
            ldsm4(bH[0],bH[1],bH[2],bH[3], vh_b + boff);
            ldsm4(bL[0],bL[1],bL[2],bL[3], vl_b + boff);
            mma_bf16(o[2*np],   pH, bH[0], bH[1]);
            mma_bf16(o[2*np],   pH, bL[0], bL[1]);
            mma_bf16(o[2*np],   pL, bH[0], bH[1]);
            mma_bf16(o[2*np+1], pH, bH[2], bH[3]);
            mma_bf16(o[2*np+1], pH, bL[2], bL[3]);
            mma_bf16(o[2*np+1], pL, bH[2], bH[3]);
        }
    }
}

__global__ __launch_bounds__(128) void attn_mma_kernel(
    const float* __restrict__ lq1, const float* __restrict__ lk1,
    const float* __restrict__ lq2, const float* __restrict__ lk2)
{
    extern __shared__ __nv_bfloat16 sm[];
    __nv_bfloat16* q1h = sm;
    __nv_bfloat16* q1l = q1h + 64*SR;
    __nv_bfloat16* q2h = q1l + 64*SR;
    __nv_bfloat16* q2l = q2h + 64*SR;
    __nv_bfloat16* k1h = q2l + 64*SR;
    __nv_bfloat16* k1l = k1h + 64*SR;
    __nv_bfloat16* k2h = k1l + 64*SR;
    __nv_bfloat16* k2l = k2h + 64*SR;
    __nv_bfloat16* vh  = k2l + 64*SR;
    __nv_bfloat16* vl  = vh  + 64*SR;

    const int tid = threadIdx.x, lane = tid & 31, warp = tid >> 5;
    const int bh = blockIdx.y, b = bh >> 3, h = bh & 7;
    const int q0 = blockIdx.x * 64;

    // load q tiles once (hi/lo, both streams)
    {
        const size_t gbase = (size_t)(b*SS + q0)*DD + h*64;
        #pragma unroll
        for (int it = 0; it < 4; ++it) {
            int idx = tid + it*128;            // 0..511
            int row = idx >> 3, c8 = (idx & 7) << 3;
            size_t go = gbase + (size_t)row*DD + c8;
            *(uint4*)&q1h[row*SR+c8] = *(const uint4*)&g_q1h[go];
            *(uint4*)&q1l[row*SR+c8] = *(const uint4*)&g_q1l[go];
            *(uint4*)&q2h[row*SR+c8] = *(const uint4*)&g_q2h[go];
            *(uint4*)&q2l[row*SR+c8] = *(const uint4*)&g_q2l[go];
        }
    }

    float o1[8][4] = {}, o2[8][4] = {};
    float m1[2] = {-1e30f, -1e30f}, l1[2] = {0.f, 0.f};
    float m2[2] = {-1e30f, -1e30f}, l2[2] = {0.f, 0.f};

    const unsigned q1h_b = smem_u32(q1h), q1l_b = smem_u32(q1l);
    const unsigned q2h_b = smem_u32(q2h), q2l_b = smem_u32(q2l);
    const unsigned k1h_b = smem_u32(k1h), k1l_b = smem_u32(k1l);
    const unsigned k2h_b = smem_u32(k2h), k2l_b = smem_u32(k2l);
    const unsigned vh_b  = smem_u32(vh),  vl_b  = smem_u32(vl);

    const int arow   = warp*16 + (lane & 7) + ((lane >> 3) & 1) * 8;
    const int acol   = ((lane >> 4) << 3);
    const int browin = (lane & 7) + ((lane >> 4) << 3);
    const int bcol   = (((lane >> 3) & 1) << 3);

    for (int kc = 0; kc < SS; kc += 64) {
        const size_t kb = (size_t)(b*SS + kc)*DD + h*64;
        const size_t vb = (size_t)(bh*64)*SS + kc;
        #pragma unroll
        for (int it = 0; it < 4; ++it) {
            int idx = tid + it*128;
            int row = idx >> 3, c8 = (idx & 7) << 3;
            size_t go = kb + (size_t)row*DD + c8;
            *(uint4*)&k1h[row*SR+c8] = *(const uint4*)&g_k1h[go];
            *(uint4*)&k1l[row*SR+c8] = *(const uint4*)&g_k1l[go];
            *(uint4*)&k2h[row*SR+c8] = *(const uint4*)&g_k2h[go];
            *(uint4*)&k2l[row*SR+c8] = *(const uint4*)&g_k2l[go];
            size_t gv = vb + (size_t)row*SS + c8;
            *(uint4*)&vh[row*SR+c8] = *(const uint4*)&g_vth[gv];
            *(uint4*)&vl[row*SR+c8] = *(const uint4*)&g_vtl[gv];
        }
        __syncthreads();
        attn_stream_tc(q1h_b, q1l_b, k1h_b, k1l_b, vh_b, vl_b,
                       arow, acol, browin, bcol, m1, l1, o1);
        attn_stream_tc(q2h_b, q2l_b, k2h_b, k2l_b, vh_b, vl_b,
                       arow, acol, browin, bcol, m2, l2, o2);
        __syncthreads();
    }

    const float lam = __expf(lq1[h]*lk1[h]) - __expf(lq2[h]*lk2[h]) + 0.2f;
    const int gid = lane >> 2, tig = lane & 3;
    const float i1[2] = {1.f/l1[0], 1.f/l1[1]};
    const float i2[2] = {lam/l2[0], lam/l2[1]};
    #pragma unroll
    for (int hf = 0; hf < 2; ++hf)
        #pragma unroll
        for (int nf = 0; nf < 8; ++nf) {
            int r = q0 + warp*16 + gid + hf*8;
            int col = h*64 + nf*8 + tig*2;
            float2 y;
            y.x = o1[nf][2*hf]  *i1[hf] - o2[nf][2*hf]  *i2[hf];
            y.y = o1[nf][2*hf+1]*i1[hf] - o2[nf][2*hf+1]*i2[hf];
            *(float2*)&g_o[(size_t)(b*SS + r)*DD + col] = y;
        }
}

// ============================================================
// Kernel 3: GroupNorm stats (unchanged)
// ============================================================
__global__ __launch_bounds__(256) void gn_stats_kernel()
{
    const int gi = blockIdx.x;           // 0..7
    const int b = gi >> 2, g = gi & 3;
    const int tid = threadIdx.x;
    const float* base = g_o + (size_t)b*SS*DD + g*128;

    float s = 0.f, ss = 0.f;
    for (int i = tid; i < SS*128; i += 256) {
        int r = i >> 7, c = i & 127;
        float v = base[(size_t)r*DD + c];
        s += v; ss += v*v;
    }
    __shared__ float rs[256], rq[256];
    rs[tid] = s; rq[tid] = ss;
    __syncthreads();
    for (int off = 128; off > 0; off >>= 1) {
        if (tid < off) { rs[tid] += rs[tid+off]; rq[tid] += rq[tid+off]; }
        __syncthreads();
    }
    if (tid == 0) {
        const float n = (float)(SS*128);
        float mu  = rs[0] / n;
        float var = rq[0] / n - mu*mu;
        g_mu[gi]   = mu;
        g_rstd[gi] = rsqrtf(var + 1e-5f);
    }
}

// ============================================================
// Kernel 4: output GEMM with GroupNorm fused (fp32, unchanged)
// ============================================================
__global__ __launch_bounds__(256) void out_kernel(
    const float* __restrict__ W, const float* __restrict__ bias,
    const float* __restrict__ gw, const float* __restrict__ gb,
    float* __restrict__ y)
{
    __shared__ float As[32*SP];
    __shared__ float Bs[32*SP];

    const int tid = threadIdx.x;
    const int tx = tid & 15, ty = tid >> 4;
    const int m0 = blockIdx.x * 64;
    const int n0 = blockIdx.y * 64;
    const int b  = m0 >> 11;

    float acc[4][4] = {};

    for (int k0 = 0; k0 < DD; k0 += 32) {
        #pragma unroll
        for (int t = 0; t < 2; ++t) {
            int f = tid + t * 256;
            int row = f >> 3;
            int kk  = (f & 7) << 2;
            int c   = k0 + kk;
            int gi  = b*4 + (c >> 7);
            float mu = g_mu[gi], rst = g_rstd[gi];
            float4 a4 = *(const float4*)&g_o[(size_t)(m0+row)*DD + c];
            float4 w4 = *(const float4*)&gw[c];
            float4 s4 = *(const float4*)&gb[c];
            As[(kk+0)*SP+row] = (a4.x - mu)*rst*w4.x + s4.x;
            As[(kk+1)*SP+row] = (a4.y - mu)*rst*w4.y + s4.y;
            As[(kk+2)*SP+row] = (a4.z - mu)*rst*w4.z + s4.z;
            As[(kk+3)*SP+row] = (a4.w - mu)*rst*w4.w + s4.w;
            float4 b4 = *(const float4*)&W[(size_t)(n0+row)*DD + k0 + kk];
            Bs[(kk+0)*SP+row] = b4.x; Bs[(kk+1)*SP+row] = b4.y;
            Bs[(kk+2)*SP+row] = b4.z; Bs[(kk+3)*SP+row] = b4.w;
        }
        __syncthreads();
        #pragma unroll 8
        for (int kk = 0; kk < 32; ++kk) {
            float4 a4 = *(const float4*)&As[kk*SP + 4*ty];
            float4 b4 = *(const float4*)&Bs[kk*SP + 4*tx];
            float a[4] = {a4.x, a4.y, a4.z, a4.w};
            float bb[4] = {b4.x, b4.y, b4.z, b4.w};
            #pragma unroll
            for (int i = 0; i < 4; ++i)
                #pragma unroll
                for (int j = 0; j < 4; ++j)
                    acc[i][j] = fmaf(a[i], bb[j], acc[i][j]);
        }
        __syncthreads();
    }

    float bv[4];
    #pragma unroll
    for (int j = 0; j < 4; ++j) bv[j] = bias[n0 + 4*tx + j];
    #pragma unroll
    for (int i = 0; i < 4; ++i) {
        float4 r;
        r.x = acc[i][0] + bv[0]; r.y = acc[i][1] + bv[1];
        r.z = acc[i][2] + bv[2]; r.w = acc[i][3] + bv[3];
        *(float4*)&y[(size_t)(m0 + 4*ty + i)*DD + n0 + 4*tx] = r;
    }
}

// ============================================================
// launch
// ============================================================
extern "C" void kernel_launch(void* const* d_in, const int* in_sizes, int n_in,
                              void* d_out, int out_size)
{
    const float* x   = (const float*)d_in[0];
    const float* K1w = (const float*)d_in[1];
    const float* K1b = (const float*)d_in[2];
    const float* Q1w = (const float*)d_in[3];
    const float* K2w = (const float*)d_in[4];
    const float* K2b = (const float*)d_in[5];
    const float* Q2w = (const float*)d_in[6];
    const float* Vw  = (const float*)d_in[7];
    const float* lq1 = (const float*)d_in[8];
    const float* lk1 = (const float*)d_in[9];
    const float* lq2 = (const float*)d_in[10];
    const float* lk2 = (const float*)d_in[11];
    const float* gw  = (const float*)d_in[12];
    const float* gb  = (const float*)d_in[13];
    const float* Ow  = (const float*)d_in[14];
    const float* Ob  = (const float*)d_in[15];
    float* y = (float*)d_out;

    const int ATT_SMEM = 10 * 64 * SR * (int)sizeof(__nv_bfloat16);  // 92160 B
    cudaFuncSetAttribute(attn_mma_kernel,
                         cudaFuncAttributeMaxDynamicSharedMemorySize, ATT_SMEM);

    qkv_mma_kernel<<<dim3(NROW/64, DD/64, 5), 128>>>(x, Q1w, K1w, K1b, Q2w, K2w, K2b, Vw);
    attn_mma_kernel<<<dim3(SS/64, BB*HH), 128, ATT_SMEM>>>(lq1, lk1, lq2, lk2);
    gn_stats_kernel<<<BB*GG, 256>>>();
    out_kernel<<<dim3(NROW/64, DD/64), 256>>>(Ow, Ob, gw, gb, y);
}